// round 3
// baseline (speedup 1.0000x reference)
#include <cuda_runtime.h>
#include <cstdint>

// Problem constants (fixed by the dataset)
#define Nn 50000
#define Ee 640000
#define INDIM 128
#define Hh 4
#define Cc 32
#define Rr 8
#define HC 128          // H*C
#define NSEG (Rr*Nn)    // 400000

// ---------------- device scratch (allocation-free rule: __device__ globals) ----
__device__ __align__(16) float g_hj[(size_t)Nn*HC];
__device__ __align__(16) float g_hi[(size_t)Nn*HC];
__device__ __align__(16) float g_selfnode[(size_t)Nn*HC];
__device__ __align__(16) float g_selfterm[(size_t)Nn*Cc];
__device__ float g_ai[(size_t)Nn*Rr*Hh];
__device__ float g_aj[(size_t)Nn*Rr*Hh];
__device__ float g_amax[(size_t)NSEG*Hh];
__device__ float g_denom[(size_t)NSEG*Hh];
__device__ float g_ex[(size_t)Ee*Hh];
__device__ __align__(16) float g_agg[(size_t)NSEG*HC];   // 204.8 MB
__device__ float g_q[(size_t)NSEG*Cc];
__device__ float g_k[(size_t)NSEG*Cc];
__device__ float g_v[(size_t)NSEG*Cc];
// normalized edge arrays (robust to int32 vs int64 inputs)
__device__ int g_src[Ee];
__device__ int g_dst[Ee];
__device__ int g_rel[Ee];
__device__ int g_is64;

// ---------------- helpers ------------------------------------------------------
__device__ __forceinline__ void atomicMaxF(float* addr, float v) {
    if (v >= 0.f) atomicMax((int*)addr, __float_as_int(v));
    else          atomicMin((unsigned int*)addr, __float_as_uint(v));
}

// ---------------- K_detect: int64 vs int32 edge_index -------------------------
__global__ void k_detect(const int* __restrict__ ei_raw) {
    if (threadIdx.x == 0 && blockIdx.x == 0) {
        // If data is int64 with values < 2^31, every odd 32-bit word is 0.
        int allzero = 1;
        for (int i = 1; i < 256; i += 2) {
            if (ei_raw[i] != 0) { allzero = 0; break; }
        }
        g_is64 = allzero;
    }
}

// ---------------- K_convert: normalize edge arrays ----------------------------
__global__ void k_convert(const void* __restrict__ ei_raw,
                          const void* __restrict__ et_raw) {
    int e = blockIdx.x * blockDim.x + threadIdx.x;
    if (e >= Ee) return;
    if (g_is64) {
        const long long* ei = (const long long*)ei_raw;
        const long long* et = (const long long*)et_raw;
        g_src[e] = (int)ei[e];
        g_dst[e] = (int)ei[Ee + e];
        g_rel[e] = (int)et[e];
    } else {
        const int* ei = (const int*)ei_raw;
        const int* et = (const int*)et_raw;
        g_src[e] = ei[e];
        g_dst[e] = ei[Ee + e];
        g_rel[e] = et[e];
    }
}

// ---------------- K0: init scratch (graph replays must re-init) ---------------
__global__ void k_init() {
    int i = blockIdx.x * blockDim.x + threadIdx.x;
    int stride = gridDim.x * blockDim.x;
    const float ninf = __int_as_float(0xff800000);
    for (int j = i; j < NSEG*Hh; j += stride) { g_amax[j] = ninf; g_denom[j] = 0.f; }
    float4 z = make_float4(0.f,0.f,0.f,0.f);
    float4* a4 = (float4*)g_agg;
    long total4 = (long)NSEG*HC/4;
    for (long j = i; j < total4; j += stride) a4[j] = z;
}

// ---------------- K1: fused input GEMM  x[N,128] @ {Wj,Wi,Wsn,Wself} ----------
__global__ void k_gemm_x(const float* __restrict__ x,
                         const float* __restrict__ Wj,
                         const float* __restrict__ Wi,
                         const float* __restrict__ Wsn,
                         const float* __restrict__ Wself) {
    int mat = blockIdx.z;
    int width = (mat == 3) ? Cc : HC;
    int col0 = blockIdx.x * 64;
    if (col0 >= width) return;
    int row0 = blockIdx.y * 64;
    const float* W = (mat==0) ? Wj : (mat==1) ? Wi : (mat==2) ? Wsn : Wself;
    float* out = (mat==0) ? g_hj : (mat==1) ? g_hi : (mat==2) ? g_selfnode : g_selfterm;

    __shared__ float xs[64][33];
    __shared__ float ws[32*64];
    int tx = threadIdx.x, ty = threadIdx.y;
    int tid = ty*16 + tx;
    float acc[4][4] = {};

    for (int kb = 0; kb < INDIM; kb += 32) {
        #pragma unroll
        for (int i = 0; i < 8; i++) {
            int e = tid + i*256;
            int rr = e >> 5, kk = e & 31;
            int gr = row0 + rr;
            xs[rr][kk] = (gr < Nn) ? x[(size_t)gr*INDIM + kb + kk] : 0.f;
        }
        #pragma unroll
        for (int i = 0; i < 8; i++) {
            int e = tid + i*256;
            int kk = e >> 6, cc = e & 63;
            int gc = col0 + cc;
            ws[kk*64 + cc] = (gc < width) ? W[(size_t)(kb+kk)*width + gc] : 0.f;
        }
        __syncthreads();
        #pragma unroll
        for (int k = 0; k < 32; k++) {
            float a[4];
            #pragma unroll
            for (int i = 0; i < 4; i++) a[i] = xs[ty*4+i][k];
            float b[4];
            #pragma unroll
            for (int j = 0; j < 4; j++) b[j] = ws[k*64 + tx*4 + j];
            #pragma unroll
            for (int i = 0; i < 4; i++)
                #pragma unroll
                for (int j = 0; j < 4; j++)
                    acc[i][j] = fmaf(a[i], b[j], acc[i][j]);
        }
        __syncthreads();
    }
    #pragma unroll
    for (int i = 0; i < 4; i++) {
        int gr = row0 + ty*4 + i;
        if (gr >= Nn) continue;
        #pragma unroll
        for (int j = 0; j < 4; j++) {
            int gc = col0 + tx*4 + j;
            if (gc < width) out[(size_t)gr*width + gc] = acc[i][j];
        }
    }
}

// ---------------- K2: per-node attention coefficients ai/aj -------------------
__global__ void k_attcoef(const float* __restrict__ node_att) {
    int idx = blockIdx.x * blockDim.x + threadIdx.x;
    if (idx >= Nn*32) return;
    int n = idx >> 5, p = idx & 31;        // p = r*H + h
    int h = p & 3;
    const float* att = node_att + p*64;    // [r,h, 2C]
    const float* hi = g_hi + (size_t)n*HC + h*Cc;
    const float* hj = g_hj + (size_t)n*HC + h*Cc;
    float si = 0.f, sj = 0.f;
    #pragma unroll
    for (int c = 0; c < 32; c++) {
        si = fmaf(att[c],    hi[c], si);
        sj = fmaf(att[32+c], hj[c], sj);
    }
    g_ai[idx] = si;
    g_aj[idx] = sj;
}

// ---------------- K3: per-edge alpha + leaky relu + segment max ---------------
__global__ void k_alpha() {
    int idx = blockIdx.x * blockDim.x + threadIdx.x;
    if (idx >= Ee*Hh) return;
    int e = idx >> 2, h = idx & 3;
    int s = g_src[e], d = g_dst[e], r = g_rel[e];
    float a = g_ai[d*32 + r*4 + h] + g_aj[s*32 + r*4 + h];
    a = (a >= 0.f) ? a : 0.2f*a;           // leaky_relu 0.2
    g_ex[idx] = a;
    atomicMaxF(&g_amax[(r*Nn + d)*4 + h], a);
}

// ---------------- K4: exp(alpha - max) + segment sum --------------------------
__global__ void k_expsum() {
    int idx = blockIdx.x * blockDim.x + threadIdx.x;
    if (idx >= Ee*Hh) return;
    int e = idx >> 2, h = idx & 3;
    int d = g_dst[e], r = g_rel[e];
    int seg = r*Nn + d;
    float ex = expf(g_ex[idx] - g_amax[seg*4 + h]);
    g_ex[idx] = ex;
    atomicAdd(&g_denom[seg*4 + h], ex);
}

// ---------------- K5: message scatter (warp per edge) -------------------------
__global__ void k_scatter() {
    int w = (blockIdx.x * blockDim.x + threadIdx.x) >> 5;
    int l = threadIdx.x & 31;
    if (w >= Ee) return;
    int s = g_src[w], d = g_dst[w], r = g_rel[w];
    int seg = r*Nn + d;
    int h = l >> 3;                          // 8 lanes per head (4 floats each)
    float coef = g_ex[w*4 + h] / (g_denom[seg*4 + h] + 1e-16f);
    float4 xj = ((const float4*)(g_hj + (size_t)s*HC))[l];
    float* base = g_agg + (size_t)seg*HC + l*4;
    atomicAdd(base+0, coef*xj.x);
    atomicAdd(base+1, coef*xj.y);
    atomicAdd(base+2, coef*xj.z);
    atomicAdd(base+3, coef*xj.w);
}

// ---------------- K6: per-relation QKV GEMM  (agg+selfnode)[N,128]@[128,96] ---
__global__ void k_qkv(const float* __restrict__ Wq,
                      const float* __restrict__ Wk,
                      const float* __restrict__ Wv) {
    int r = blockIdx.z;
    int row0 = blockIdx.y * 64;
    __shared__ float zs[64][33];
    __shared__ float ws[32*97];
    int tx = threadIdx.x, ty = threadIdx.y;   // (16,16)
    int tid = ty*16 + tx;
    float acc[4][6] = {};

    for (int kb = 0; kb < INDIM; kb += 32) {
        #pragma unroll
        for (int i = 0; i < 8; i++) {
            int e = tid + i*256;
            int rr = e >> 5, kk = e & 31;
            int gr = row0 + rr;
            float val = 0.f;
            if (gr < Nn)
                val = g_agg[((size_t)(r*Nn + gr))*HC + kb + kk]
                    + g_selfnode[(size_t)gr*HC + kb + kk];
            zs[rr][kk] = val;
        }
        #pragma unroll
        for (int i = 0; i < 12; i++) {
            int e = tid + i*256;              // 3072 = 32*96
            int kk = e / 96, cc = e % 96;
            int sel = cc >> 5, lc = cc & 31;
            const float* Wsel = (sel==0) ? Wq : (sel==1) ? Wk : Wv;
            ws[kk*97 + cc] = Wsel[(size_t)r*4096 + (kb+kk)*32 + lc];
        }
        __syncthreads();
        #pragma unroll
        for (int k = 0; k < 32; k++) {
            float a[4];
            #pragma unroll
            for (int i = 0; i < 4; i++) a[i] = zs[ty*4+i][k];
            float b[6];
            #pragma unroll
            for (int j = 0; j < 6; j++) b[j] = ws[k*97 + tx*6 + j];
            #pragma unroll
            for (int i = 0; i < 4; i++)
                #pragma unroll
                for (int j = 0; j < 6; j++)
                    acc[i][j] = fmaf(a[i], b[j], acc[i][j]);
        }
        __syncthreads();
    }
    #pragma unroll
    for (int i = 0; i < 4; i++) {
        int gr = row0 + ty*4 + i;
        if (gr >= Nn) continue;
        #pragma unroll
        for (int j = 0; j < 6; j++) {
            int gc = tx*6 + j;
            int sel = gc >> 5, lc = gc & 31;
            float* o = (sel==0) ? g_q : (sel==1) ? g_k : g_v;
            o[((size_t)(r*Nn + gr))*Cc + lc] = acc[i][j];
        }
    }
}

// ---------------- K7: relation attention + output (warp per node) -------------
__global__ void k_final(const float* __restrict__ Wrel, float* __restrict__ out) {
    int w = (blockIdx.x * blockDim.x + threadIdx.x) >> 5;
    int l = threadIdx.x & 31;
    if (w >= Nn) return;
    int n = w;
    float q[Rr], kk[Rr], vv[Rr];
    #pragma unroll
    for (int r = 0; r < Rr; r++) {
        int base = (r*Nn + n)*Cc + l;
        q[r]  = g_q[base];
        kk[r] = g_k[base];
        vv[r] = g_v[base];
    }
    float st = g_selfterm[(size_t)n*Cc + l];
    float acc = 0.f;
    #pragma unroll
    for (int r = 0; r < Rr; r++) {
        float p[Rr];
        #pragma unroll
        for (int s = 0; s < Rr; s++) {
            float t = q[r] * kk[s];
            #pragma unroll
            for (int o = 16; o > 0; o >>= 1) t += __shfl_xor_sync(0xffffffffu, t, o);
            p[s] = t;
        }
        float m = p[0];
        #pragma unroll
        for (int s = 1; s < Rr; s++) m = fmaxf(m, p[s]);
        float sum = 0.f;
        #pragma unroll
        for (int s = 0; s < Rr; s++) { p[s] = expf(p[s] - m); sum += p[s]; }
        float inv = 1.f / sum;
        float delta = 0.f;
        #pragma unroll
        for (int s = 0; s < Rr; s++) delta = fmaf(p[s]*inv, vv[s], delta);
        float sd = delta;
        #pragma unroll
        for (int o = 16; o > 0; o >>= 1) sd += __shfl_xor_sync(0xffffffffu, sd, o);
        float mask = (sd != 0.f) ? 1.f : 0.f;
        acc = fmaf(Wrel[r], delta + st*mask, acc);
    }
    out[(size_t)n*Cc + l] = acc;
}

// ---------------- launcher ----------------------------------------------------
extern "C" void kernel_launch(void* const* d_in, const int* in_sizes, int n_in,
                              void* d_out, int out_size) {
    const float* x     = (const float*)d_in[0];
    const void*  ei    = d_in[1];
    const void*  et    = d_in[2];
    const float* Wj    = (const float*)d_in[3];
    const float* Wi    = (const float*)d_in[4];
    const float* natt  = (const float*)d_in[5];
    const float* Wq    = (const float*)d_in[6];
    const float* Wk    = (const float*)d_in[7];
    const float* Wv    = (const float*)d_in[8];
    const float* Wself = (const float*)d_in[9];
    const float* Wsn   = (const float*)d_in[10];
    const float* Wrel  = (const float*)d_in[11];
    float* out = (float*)d_out;

    k_detect<<<1, 32>>>((const int*)ei);
    k_convert<<<(Ee + 255)/256, 256>>>(ei, et);
    k_init<<<2048, 256>>>();

    dim3 b16(16, 16);
    k_gemm_x<<<dim3(2, (Nn + 63)/64, 4), b16>>>(x, Wj, Wi, Wsn, Wself);

    k_attcoef<<<(Nn*32 + 255)/256, 256>>>(natt);

    k_alpha <<<(Ee*Hh + 255)/256, 256>>>();
    k_expsum<<<(Ee*Hh + 255)/256, 256>>>();
    k_scatter<<<(Ee + 7)/8, 256>>>();

    k_qkv<<<dim3(1, (Nn + 63)/64, Rr), b16>>>(Wq, Wk, Wv);

    k_final<<<(Nn + 7)/8, 256>>>(Wrel, out);
}

// round 4
// speedup vs baseline: 1.3479x; 1.3479x over previous
#include <cuda_runtime.h>
#include <cstdint>

#define Nn 50000
#define Ee 640000
#define INDIM 128
#define Hh 4
#define Cc 32
#define Rr 8
#define HC 128
#define NSEG (Rr*Nn)          // 400000
#define SCAN_B 1024
#define SCAN_NB ((NSEG + SCAN_B - 1)/SCAN_B)   // 391

// ---------------- device scratch ----------------------------------------------
__device__ __align__(16) float g_hj[(size_t)Nn*HC];
__device__ __align__(16) float g_hi[(size_t)Nn*HC];
__device__ __align__(16) float g_selfnode[(size_t)Nn*HC];
__device__ __align__(16) float g_selfterm[(size_t)Nn*Cc];
__device__ float g_ai[(size_t)Nn*Rr*Hh];
__device__ float g_aj[(size_t)Nn*Rr*Hh];
__device__ __align__(16) float g_z[(size_t)NSEG*HC];     // z = agg + selfnode (204.8MB)
__device__ float g_q[(size_t)NSEG*Cc];
__device__ float g_k[(size_t)NSEG*Cc];
__device__ float g_v[(size_t)NSEG*Cc];
// edge arrays + sort scratch
__device__ int g_src[Ee];
__device__ int g_dst[Ee];
__device__ int g_rel[Ee];
__device__ int g_hist[NSEG];
__device__ int g_fill[NSEG];
__device__ int g_off[NSEG+1];
__device__ int g_bsum[SCAN_NB];
__device__ int g_boff[SCAN_NB];
__device__ int g_sorted[Ee];
__device__ int g_is64;

// ---------------- K_detect: int64 vs int32 edge_index -------------------------
__global__ void k_detect(const int* __restrict__ ei_raw) {
    if (threadIdx.x == 0 && blockIdx.x == 0) {
        int allzero = 1;
        for (int i = 1; i < 256; i += 2)
            if (ei_raw[i] != 0) { allzero = 0; break; }
        g_is64 = allzero;
    }
}

// ---------------- K_zero: zero histogram + fill counters ----------------------
__global__ void k_zero() {
    int i = blockIdx.x * blockDim.x + threadIdx.x;
    int stride = gridDim.x * blockDim.x;
    for (int j = i; j < NSEG; j += stride) { g_hist[j] = 0; g_fill[j] = 0; }
}

// ---------------- K_convert: normalize edges + histogram ----------------------
__global__ void k_convert(const void* __restrict__ ei_raw,
                          const void* __restrict__ et_raw) {
    int e = blockIdx.x * blockDim.x + threadIdx.x;
    if (e >= Ee) return;
    int s, d, r;
    if (g_is64) {
        const long long* ei = (const long long*)ei_raw;
        const long long* et = (const long long*)et_raw;
        s = (int)ei[e]; d = (int)ei[Ee + e]; r = (int)et[e];
    } else {
        const int* ei = (const int*)ei_raw;
        const int* et = (const int*)et_raw;
        s = ei[e]; d = ei[Ee + e]; r = et[e];
    }
    g_src[e] = s; g_dst[e] = d; g_rel[e] = r;
    atomicAdd(&g_hist[r*Nn + d], 1);
}

// ---------------- scan (3 kernels) --------------------------------------------
__global__ void k_scan1() {
    __shared__ int sh[SCAN_B];
    int t = threadIdx.x;
    int i = blockIdx.x * SCAN_B + t;
    int v = (i < NSEG) ? g_hist[i] : 0;
    sh[t] = v;
    __syncthreads();
    for (int off = 1; off < SCAN_B; off <<= 1) {
        int t2 = (t >= off) ? sh[t - off] : 0;
        __syncthreads();
        if (t >= off) sh[t] += t2;
        __syncthreads();
    }
    if (i < NSEG) g_off[i] = sh[t] - v;      // exclusive within block
    if (t == SCAN_B - 1) g_bsum[blockIdx.x] = sh[t];
}
__global__ void k_scan2() {
    __shared__ int sh[512];
    int t = threadIdx.x;
    int v = (t < SCAN_NB) ? g_bsum[t] : 0;
    sh[t] = v;
    __syncthreads();
    for (int off = 1; off < 512; off <<= 1) {
        int t2 = (t >= off) ? sh[t - off] : 0;
        __syncthreads();
        if (t >= off) sh[t] += t2;
        __syncthreads();
    }
    if (t < SCAN_NB) g_boff[t] = sh[t] - v;  // exclusive
}
__global__ void k_scan3() {
    int t = threadIdx.x;
    int i = blockIdx.x * SCAN_B + t;
    if (i < NSEG) g_off[i] += g_boff[blockIdx.x];
    if (i == 0) g_off[NSEG] = Ee;
}

// ---------------- K_reorder: counting-sort edge ids by segment ----------------
__global__ void k_reorder() {
    int e = blockIdx.x * blockDim.x + threadIdx.x;
    if (e >= Ee) return;
    int seg = g_rel[e]*Nn + g_dst[e];
    int pos = g_off[seg] + atomicAdd(&g_fill[seg], 1);
    g_sorted[pos] = e;
}

// ---------------- K1: input GEMM x[N,128] @ {Wj,Wi,Wsn,Wself} -----------------
__global__ void __launch_bounds__(256) k_gemm_x(
        const float* __restrict__ x,
        const float* __restrict__ Wj,
        const float* __restrict__ Wi,
        const float* __restrict__ Wsn,
        const float* __restrict__ Wself) {
    int mat = blockIdx.z;
    int width = (mat == 3) ? Cc : HC;
    int col0 = blockIdx.x * 64;
    if (col0 >= width) return;
    int row0 = blockIdx.y * 128;
    const float* W = (mat==0) ? Wj : (mat==1) ? Wi : (mat==2) ? Wsn : Wself;
    float* out = (mat==0) ? g_hj : (mat==1) ? g_hi : (mat==2) ? g_selfnode : g_selfterm;

    __shared__ float zs[128][17];
    __shared__ alignas(16) float ws[16][68];
    int tid = threadIdx.x;
    int tx = tid & 15, ty = tid >> 4;
    float acc[8][4] = {};

    for (int kb = 0; kb < INDIM; kb += 16) {
        #pragma unroll
        for (int i = 0; i < 8; i++) {
            int idx = tid + i*256;
            int rr = idx >> 4, kk = idx & 15;
            int gr = row0 + rr;
            zs[rr][kk] = (gr < Nn) ? x[(size_t)gr*INDIM + kb + kk] : 0.f;
        }
        #pragma unroll
        for (int i = 0; i < 4; i++) {
            int idx = tid + i*256;
            int kk = idx >> 6, cc = idx & 63;
            int gc = col0 + cc;
            ws[kk][cc] = (gc < width) ? W[(size_t)(kb+kk)*width + gc] : 0.f;
        }
        __syncthreads();
        #pragma unroll
        for (int k = 0; k < 16; k++) {
            float4 b4 = *(const float4*)&ws[k][tx*4];
            float b[4] = {b4.x, b4.y, b4.z, b4.w};
            #pragma unroll
            for (int i = 0; i < 8; i++) {
                float a = zs[ty*8+i][k];
                #pragma unroll
                for (int j = 0; j < 4; j++)
                    acc[i][j] = fmaf(a, b[j], acc[i][j]);
            }
        }
        __syncthreads();
    }
    #pragma unroll
    for (int i = 0; i < 8; i++) {
        int gr = row0 + ty*8 + i;
        if (gr >= Nn) continue;
        #pragma unroll
        for (int j = 0; j < 4; j++) {
            int gc = col0 + tx*4 + j;
            if (gc < width) out[(size_t)gr*width + gc] = acc[i][j];
        }
    }
}

// ---------------- K2: per-node attention coefficients -------------------------
__global__ void k_attcoef(const float* __restrict__ node_att) {
    int idx = blockIdx.x * blockDim.x + threadIdx.x;
    if (idx >= Nn*32) return;
    int n = idx >> 5, p = idx & 31;
    int h = p & 3;
    const float* att = node_att + p*64;
    const float* hi = g_hi + (size_t)n*HC + h*Cc;
    const float* hj = g_hj + (size_t)n*HC + h*Cc;
    float si = 0.f, sj = 0.f;
    #pragma unroll
    for (int c = 0; c < 32; c++) {
        si = fmaf(att[c],    hi[c], si);
        sj = fmaf(att[32+c], hj[c], sj);
    }
    g_ai[idx] = si;
    g_aj[idx] = sj;
}

// ---------------- K_seg: warp per segment — softmax + aggregate + selfnode ----
__global__ void k_seg() {
    int w = (blockIdx.x * blockDim.x + threadIdx.x) >> 5;
    if (w >= NSEG) return;
    int l = threadIdx.x & 31;
    int r = w / Nn;
    int n = w - r*Nn;
    int h = l >> 3;
    int begin = g_off[w], end = g_off[w+1];

    float ain = g_ai[n*32 + r*4 + h];      // dst == n for this segment
    // pass 1: max over edges (per head)
    float m = __int_as_float(0xff800000);
    for (int i = begin; i < end; i++) {
        int e = g_sorted[i];
        int s = g_src[e];
        float a = ain + g_aj[s*32 + r*4 + h];
        a = (a >= 0.f) ? a : 0.2f*a;
        m = fmaxf(m, a);
    }
    // pass 2: exp-sum + weighted vector accumulate
    float sumex = 0.f;
    float4 acc = make_float4(0.f, 0.f, 0.f, 0.f);
    for (int i = begin; i < end; i++) {
        int e = g_sorted[i];
        int s = g_src[e];
        float a = ain + g_aj[s*32 + r*4 + h];
        a = (a >= 0.f) ? a : 0.2f*a;
        float ex = __expf(a - m);
        sumex += ex;
        float4 xj = ((const float4*)(g_hj + (size_t)s*HC))[l];
        acc.x = fmaf(ex, xj.x, acc.x);
        acc.y = fmaf(ex, xj.y, acc.y);
        acc.z = fmaf(ex, xj.z, acc.z);
        acc.w = fmaf(ex, xj.w, acc.w);
    }
    float inv = 1.f / (sumex + 1e-16f);
    float4 self = ((const float4*)(g_selfnode + (size_t)n*HC))[l];
    float4 zv;
    zv.x = fmaf(acc.x, inv, self.x);
    zv.y = fmaf(acc.y, inv, self.y);
    zv.z = fmaf(acc.z, inv, self.z);
    zv.w = fmaf(acc.w, inv, self.w);
    ((float4*)(g_z + (size_t)w*HC))[l] = zv;
}

// ---------------- K6: per-relation QKV GEMM  z[N,128]@[128,96] ----------------
__global__ void __launch_bounds__(256) k_qkv(
        const float* __restrict__ Wq,
        const float* __restrict__ Wk,
        const float* __restrict__ Wv) {
    int r = blockIdx.y;
    int row0 = blockIdx.x * 128;
    __shared__ float zs[128][17];
    __shared__ alignas(16) float ws[16][98];
    int tid = threadIdx.x;
    int tx = tid & 15, ty = tid >> 4;
    float acc[8][6] = {};

    for (int kb = 0; kb < INDIM; kb += 16) {
        #pragma unroll
        for (int i = 0; i < 8; i++) {
            int idx = tid + i*256;
            int rr = idx >> 4, kk = idx & 15;
            int gr = row0 + rr;
            zs[rr][kk] = (gr < Nn) ? g_z[((size_t)(r*Nn + gr))*HC + kb + kk] : 0.f;
        }
        #pragma unroll
        for (int i = 0; i < 6; i++) {
            int idx = tid + i*256;          // 1536 = 16*96
            int kk = idx / 96, cc = idx - kk*96;
            int sel = cc >> 5, lc = cc & 31;
            const float* Wsel = (sel==0) ? Wq : (sel==1) ? Wk : Wv;
            ws[kk][cc] = Wsel[(size_t)r*4096 + (kb+kk)*32 + lc];
        }
        __syncthreads();
        #pragma unroll
        for (int k = 0; k < 16; k++) {
            float b[6];
            float2 b0 = *(const float2*)&ws[k][tx*6 + 0];
            float2 b1 = *(const float2*)&ws[k][tx*6 + 2];
            float2 b2 = *(const float2*)&ws[k][tx*6 + 4];
            b[0]=b0.x; b[1]=b0.y; b[2]=b1.x; b[3]=b1.y; b[4]=b2.x; b[5]=b2.y;
            #pragma unroll
            for (int i = 0; i < 8; i++) {
                float a = zs[ty*8+i][k];
                #pragma unroll
                for (int j = 0; j < 6; j++)
                    acc[i][j] = fmaf(a, b[j], acc[i][j]);
            }
        }
        __syncthreads();
    }
    #pragma unroll
    for (int i = 0; i < 8; i++) {
        int gr = row0 + ty*8 + i;
        if (gr >= Nn) continue;
        #pragma unroll
        for (int j = 0; j < 6; j++) {
            int gc = tx*6 + j;
            int sel = gc >> 5, lc = gc & 31;
            float* o = (sel==0) ? g_q : (sel==1) ? g_k : g_v;
            o[((size_t)(r*Nn + gr))*Cc + lc] = acc[i][j];
        }
    }
}

// ---------------- K7: relation attention + output (warp per node) -------------
__global__ void k_final(const float* __restrict__ Wrel, float* __restrict__ out) {
    int w = (blockIdx.x * blockDim.x + threadIdx.x) >> 5;
    int l = threadIdx.x & 31;
    if (w >= Nn) return;
    int n = w;
    float q[Rr], kk[Rr], vv[Rr];
    #pragma unroll
    for (int r = 0; r < Rr; r++) {
        int base = (r*Nn + n)*Cc + l;
        q[r]  = g_q[base];
        kk[r] = g_k[base];
        vv[r] = g_v[base];
    }
    float st = g_selfterm[(size_t)n*Cc + l];
    float acc = 0.f;
    #pragma unroll
    for (int r = 0; r < Rr; r++) {
        float p[Rr];
        #pragma unroll
        for (int s = 0; s < Rr; s++) {
            float t = q[r] * kk[s];
            #pragma unroll
            for (int o = 16; o > 0; o >>= 1) t += __shfl_xor_sync(0xffffffffu, t, o);
            p[s] = t;
        }
        float m = p[0];
        #pragma unroll
        for (int s = 1; s < Rr; s++) m = fmaxf(m, p[s]);
        float sum = 0.f;
        #pragma unroll
        for (int s = 0; s < Rr; s++) { p[s] = expf(p[s] - m); sum += p[s]; }
        float inv = 1.f / sum;
        float delta = 0.f;
        #pragma unroll
        for (int s = 0; s < Rr; s++) delta = fmaf(p[s]*inv, vv[s], delta);
        float sd = delta;
        #pragma unroll
        for (int o = 16; o > 0; o >>= 1) sd += __shfl_xor_sync(0xffffffffu, sd, o);
        float mask = (sd != 0.f) ? 1.f : 0.f;
        acc = fmaf(Wrel[r], delta + st*mask, acc);
    }
    out[(size_t)n*Cc + l] = acc;
}

// ---------------- launcher ----------------------------------------------------
extern "C" void kernel_launch(void* const* d_in, const int* in_sizes, int n_in,
                              void* d_out, int out_size) {
    const float* x     = (const float*)d_in[0];
    const void*  ei    = d_in[1];
    const void*  et    = d_in[2];
    const float* Wj    = (const float*)d_in[3];
    const float* Wi    = (const float*)d_in[4];
    const float* natt  = (const float*)d_in[5];
    const float* Wq    = (const float*)d_in[6];
    const float* Wk    = (const float*)d_in[7];
    const float* Wv    = (const float*)d_in[8];
    const float* Wself = (const float*)d_in[9];
    const float* Wsn   = (const float*)d_in[10];
    const float* Wrel  = (const float*)d_in[11];
    float* out = (float*)d_out;

    k_detect<<<1, 32>>>((const int*)ei);
    k_zero<<<400, 256>>>();
    k_convert<<<(Ee + 255)/256, 256>>>(ei, et);
    k_scan1<<<SCAN_NB, SCAN_B>>>();
    k_scan2<<<1, 512>>>();
    k_scan3<<<SCAN_NB, SCAN_B>>>();
    k_reorder<<<(Ee + 255)/256, 256>>>();

    k_gemm_x<<<dim3(2, (Nn + 127)/128, 4), 256>>>(x, Wj, Wi, Wsn, Wself);
    k_attcoef<<<(Nn*32 + 255)/256, 256>>>(natt);
    k_seg<<<(NSEG + 7)/8, 256>>>();
    k_qkv<<<dim3((Nn + 127)/128, Rr), 256>>>(Wq, Wk, Wv);
    k_final<<<(Nn + 7)/8, 256>>>(Wrel, out);
}